// round 2
// baseline (speedup 1.0000x reference)
#include <cuda_runtime.h>
#include <math.h>

#define D_MODEL 512
#define HEADS   8
#define DKH     64
#define SEQ     2048
#define BATCH   4
#define D_FF    1024
#define NROWS   (BATCH*SEQ)   // 8192

// Scratch (static device arrays — no allocation at runtime)
__device__ float g_x [NROWS * D_MODEL];   // running residual stream
__device__ float g_xn[NROWS * D_MODEL];   // layernorm output
__device__ float g_h [NROWS * D_FF];      // FFN hidden

// ---------------------------------------------------------------------------
// LayerNorm: one block per row (512 elems), 128 threads x float4
// ---------------------------------------------------------------------------
__global__ void ln_kernel(const float* __restrict__ x,
                          const float* __restrict__ gamma,
                          const float* __restrict__ beta,
                          float* __restrict__ y) {
    int row = blockIdx.x;
    int t   = threadIdx.x;
    const float4* xr = (const float4*)(x + (size_t)row * D_MODEL);
    float4 v = xr[t];
    float s  = v.x + v.y + v.z + v.w;
    float ss = v.x*v.x + v.y*v.y + v.z*v.z + v.w*v.w;
    #pragma unroll
    for (int o = 16; o > 0; o >>= 1) {
        s  += __shfl_xor_sync(0xffffffffu, s,  o);
        ss += __shfl_xor_sync(0xffffffffu, ss, o);
    }
    __shared__ float as[4], ass[4];
    int w = t >> 5;
    if ((t & 31) == 0) { as[w] = s; ass[w] = ss; }
    __syncthreads();
    s  = as[0]  + as[1]  + as[2]  + as[3];
    ss = ass[0] + ass[1] + ass[2] + ass[3];
    float mu  = s * (1.0f / D_MODEL);
    float var = ss * (1.0f / D_MODEL) - mu * mu;
    float rs  = rsqrtf(var + 1e-5f);
    float4 g4 = ((const float4*)gamma)[t];
    float4 b4 = ((const float4*)beta)[t];
    float4 o4;
    o4.x = (v.x - mu) * rs * g4.x + b4.x;
    o4.y = (v.y - mu) * rs * g4.y + b4.y;
    o4.z = (v.z - mu) * rs * g4.z + b4.z;
    o4.w = (v.w - mu) * rs * g4.w + b4.w;
    ((float4*)(y + (size_t)row * D_MODEL))[t] = o4;
}

// ---------------------------------------------------------------------------
// Flash attention (fp32 SIMT). grid = (SEQ/64, HEADS, BATCH), block = 256.
// Q tile 64 rows; loop over 32 K-tiles of 64; online softmax.
// out[row, h*64+d] = res[row, h*64+d] + softmax(QK^T/8 (+mask)) @ V
// ---------------------------------------------------------------------------
#define ATTN_SMEM_FLOATS (64*65*3 + 64*64 + 3*64)
#define ATTN_SMEM_BYTES  (ATTN_SMEM_FLOATS * 4)

__global__ void attn_kernel(const float* __restrict__ Q,
                            const float* __restrict__ KV,
                            const int*   __restrict__ mask,   // may be null
                            const float* __restrict__ res,
                            float* __restrict__ out) {
    extern __shared__ float sm[];
    float* Qt   = sm;               // [64 kk][64 m], stride 65
    float* Kt   = Qt + 64 * 65;     // [64 kk][64 n], stride 65
    float* Vs   = Kt + 64 * 65;     // [64 n][64 d], stride 64
    float* Ps   = Vs + 64 * 64;     // [64 q][64 k], stride 65
    float* rowm = Ps + 64 * 65;
    float* rowl = rowm + 64;
    float* corr = rowl + 64;

    const int q0 = blockIdx.x * 64;
    const int h  = blockIdx.y;
    const int b  = blockIdx.z;
    const int tid = threadIdx.x;
    const int tx = tid & 15, ty = tid >> 4;

    // Load Q tile transposed: Qt[kk][m]
    {
        int m  = tid >> 2;
        int kb = (tid & 3) * 16;
        const float* qrow = Q + ((size_t)(b * SEQ + q0 + m)) * D_MODEL + h * DKH + kb;
        #pragma unroll
        for (int c = 0; c < 16; c += 4) {
            float4 v = *(const float4*)(qrow + c);
            Qt[(kb + c + 0) * 65 + m] = v.x;
            Qt[(kb + c + 1) * 65 + m] = v.y;
            Qt[(kb + c + 2) * 65 + m] = v.z;
            Qt[(kb + c + 3) * 65 + m] = v.w;
        }
    }
    if (tid < 64) { rowm[tid] = -INFINITY; rowl[tid] = 0.0f; }

    float o[4][4];
    #pragma unroll
    for (int i = 0; i < 4; i++)
        #pragma unroll
        for (int j = 0; j < 4; j++) o[i][j] = 0.0f;

    for (int kt = 0; kt < SEQ / 64; kt++) {
        const int k0 = kt * 64;
        __syncthreads();   // previous PV done (and Q load on first iter)

        // Load K transposed + V natural
        {
            int n  = tid >> 2;
            int kb = (tid & 3) * 16;
            const float* krow = KV + ((size_t)(b * SEQ + k0 + n)) * D_MODEL + h * DKH + kb;
            #pragma unroll
            for (int c = 0; c < 16; c += 4) {
                float4 v = *(const float4*)(krow + c);
                Kt[(kb + c + 0) * 65 + n] = v.x;
                Kt[(kb + c + 1) * 65 + n] = v.y;
                Kt[(kb + c + 2) * 65 + n] = v.z;
                Kt[(kb + c + 3) * 65 + n] = v.w;
                *(float4*)&Vs[n * 64 + kb + c] = v;   // V == K source tensor
            }
        }
        __syncthreads();

        // S = Q K^T (4x4 per thread)
        float s[4][4];
        #pragma unroll
        for (int i = 0; i < 4; i++)
            #pragma unroll
            for (int j = 0; j < 4; j++) s[i][j] = 0.0f;

        #pragma unroll 8
        for (int kk = 0; kk < 64; kk++) {
            float a[4], bb[4];
            #pragma unroll
            for (int i = 0; i < 4; i++) a[i]  = Qt[kk * 65 + ty * 4 + i];
            #pragma unroll
            for (int j = 0; j < 4; j++) bb[j] = Kt[kk * 65 + tx * 4 + j];
            #pragma unroll
            for (int i = 0; i < 4; i++)
                #pragma unroll
                for (int j = 0; j < 4; j++) s[i][j] += a[i] * bb[j];
        }
        #pragma unroll
        for (int i = 0; i < 4; i++)
            #pragma unroll
            for (int j = 0; j < 4; j++) s[i][j] *= 0.125f;   // 1/sqrt(64)

        if (mask != nullptr) {
            #pragma unroll
            for (int i = 0; i < 4; i++) {
                const int4 m4 = *(const int4*)(mask +
                    ((size_t)b * SEQ + (q0 + ty * 4 + i)) * SEQ + k0 + tx * 4);
                if (m4.x == 0) s[i][0] = -1e9f;
                if (m4.y == 0) s[i][1] = -1e9f;
                if (m4.z == 0) s[i][2] = -1e9f;
                if (m4.w == 0) s[i][3] = -1e9f;
            }
        }
        #pragma unroll
        for (int i = 0; i < 4; i++)
            #pragma unroll
            for (int j = 0; j < 4; j++)
                Ps[(ty * 4 + i) * 65 + tx * 4 + j] = s[i][j];
        __syncthreads();

        // Online softmax bookkeeping (one thread per row)
        if (tid < 64) {
            float* pr = Ps + tid * 65;
            float tm = -INFINITY;
            #pragma unroll 8
            for (int k = 0; k < 64; k++) tm = fmaxf(tm, pr[k]);
            float mold = rowm[tid];
            float mnew = fmaxf(mold, tm);
            float c = __expf(mold - mnew);
            float sum = 0.0f;
            #pragma unroll 8
            for (int k = 0; k < 64; k++) {
                float e = __expf(pr[k] - mnew);
                pr[k] = e;
                sum += e;
            }
            rowm[tid] = mnew;
            rowl[tid] = rowl[tid] * c + sum;
            corr[tid] = c;
        }
        __syncthreads();

        // Rescale accumulators + O += P V
        float cf[4];
        #pragma unroll
        for (int i = 0; i < 4; i++) cf[i] = corr[ty * 4 + i];
        #pragma unroll
        for (int i = 0; i < 4; i++)
            #pragma unroll
            for (int j = 0; j < 4; j++) o[i][j] *= cf[i];

        #pragma unroll 8
        for (int kk = 0; kk < 64; kk++) {
            float p[4];
            #pragma unroll
            for (int i = 0; i < 4; i++) p[i] = Ps[(ty * 4 + i) * 65 + kk];
            float4 v4 = *(const float4*)&Vs[kk * 64 + tx * 4];
            #pragma unroll
            for (int i = 0; i < 4; i++) {
                o[i][0] += p[i] * v4.x;
                o[i][1] += p[i] * v4.y;
                o[i][2] += p[i] * v4.z;
                o[i][3] += p[i] * v4.w;
            }
        }
    }

    // Epilogue: normalize + residual add
    float inv[4];
    #pragma unroll
    for (int i = 0; i < 4; i++) inv[i] = 1.0f / rowl[ty * 4 + i];
    #pragma unroll
    for (int i = 0; i < 4; i++) {
        size_t idx = ((size_t)(b * SEQ + q0 + ty * 4 + i)) * D_MODEL + h * DKH + tx * 4;
        float4 r4 = *(const float4*)(res + idx);
        float4 o4;
        o4.x = r4.x + o[i][0] * inv[i];
        o4.y = r4.y + o[i][1] * inv[i];
        o4.z = r4.z + o[i][2] * inv[i];
        o4.w = r4.w + o[i][3] * inv[i];
        *(float4*)(out + idx) = o4;
    }
}

// ---------------------------------------------------------------------------
// Tiled GEMM: C[M,N] = A[M,K] @ B[K,N] + bias (+ReLU) (+res). 64x64x16 tiles.
// grid = (N/64, M/64), block = 256, 4x4 per thread.
// ---------------------------------------------------------------------------
template<bool RELU, bool RES>
__global__ void gemm_kernel(const float* __restrict__ A,
                            const float* __restrict__ B,
                            const float* __restrict__ bias,
                            const float* __restrict__ res,
                            float* __restrict__ C,
                            int M, int N, int K) {
    __shared__ float As[16 * 65];   // As[k][m], stride 65
    __shared__ float Bs[16 * 64];   // Bs[k][n]

    const int n0 = blockIdx.x * 64;
    const int m0 = blockIdx.y * 64;
    const int tid = threadIdx.x;
    const int tx = tid & 15, ty = tid >> 4;

    float acc[4][4];
    #pragma unroll
    for (int i = 0; i < 4; i++)
        #pragma unroll
        for (int j = 0; j < 4; j++) acc[i][j] = 0.0f;

    for (int k0 = 0; k0 < K; k0 += 16) {
        {
            int m  = tid >> 2;
            int kb = (tid & 3) * 4;
            float4 av = *(const float4*)(A + (size_t)(m0 + m) * K + k0 + kb);
            As[(kb + 0) * 65 + m] = av.x;
            As[(kb + 1) * 65 + m] = av.y;
            As[(kb + 2) * 65 + m] = av.z;
            As[(kb + 3) * 65 + m] = av.w;
            int kk = tid >> 4;
            int n  = (tid & 15) * 4;
            float4 bv = *(const float4*)(B + (size_t)(k0 + kk) * N + n0 + n);
            *(float4*)&Bs[kk * 64 + n] = bv;
        }
        __syncthreads();
        #pragma unroll
        for (int kk = 0; kk < 16; kk++) {
            float a[4];
            #pragma unroll
            for (int i = 0; i < 4; i++) a[i] = As[kk * 65 + ty * 4 + i];
            float4 bv = *(const float4*)&Bs[kk * 64 + tx * 4];
            #pragma unroll
            for (int i = 0; i < 4; i++) {
                acc[i][0] += a[i] * bv.x;
                acc[i][1] += a[i] * bv.y;
                acc[i][2] += a[i] * bv.z;
                acc[i][3] += a[i] * bv.w;
            }
        }
        __syncthreads();
    }

    #pragma unroll
    for (int i = 0; i < 4; i++) {
        size_t idx = (size_t)(m0 + ty * 4 + i) * N + n0 + tx * 4;
        float4 bi = *(const float4*)(bias + n0 + tx * 4);
        float4 v;
        v.x = acc[i][0] + bi.x;
        v.y = acc[i][1] + bi.y;
        v.z = acc[i][2] + bi.z;
        v.w = acc[i][3] + bi.w;
        if (RELU) {
            v.x = fmaxf(v.x, 0.0f); v.y = fmaxf(v.y, 0.0f);
            v.z = fmaxf(v.z, 0.0f); v.w = fmaxf(v.w, 0.0f);
        }
        if (RES) {
            float4 r4 = *(const float4*)(res + idx);
            v.x += r4.x; v.y += r4.y; v.z += r4.z; v.w += r4.w;
        }
        *(float4*)(C + idx) = v;
    }
}

// ---------------------------------------------------------------------------
extern "C" void kernel_launch(void* const* d_in, const int* in_sizes, int n_in,
                              void* d_out, int out_size) {
    const float* x    = (const float*)d_in[0];
    const float* enc  = (const float*)d_in[1];
    const int*   mask = (const int*)  d_in[2];
    const float* ln1g = (const float*)d_in[3];
    const float* ln1b = (const float*)d_in[4];
    const float* ln2g = (const float*)d_in[5];
    const float* ln2b = (const float*)d_in[6];
    const float* ln3g = (const float*)d_in[7];
    const float* ln3b = (const float*)d_in[8];
    const float* W1   = (const float*)d_in[9];
    const float* b1   = (const float*)d_in[10];
    const float* W2   = (const float*)d_in[11];
    const float* b2   = (const float*)d_in[12];
    float* out = (float*)d_out;

    float *gx, *gxn, *gh;
    cudaGetSymbolAddress((void**)&gx,  g_x);
    cudaGetSymbolAddress((void**)&gxn, g_xn);
    cudaGetSymbolAddress((void**)&gh,  g_h);

    cudaFuncSetAttribute(attn_kernel,
                         cudaFuncAttributeMaxDynamicSharedMemorySize,
                         ATTN_SMEM_BYTES);

    dim3 attn_grid(SEQ / 64, HEADS, BATCH);

    // 1) x1 = LN1(x); x' = x + selfattn(x1, mask)
    ln_kernel<<<NROWS, 128>>>(x, ln1g, ln1b, gxn);
    attn_kernel<<<attn_grid, 256, ATTN_SMEM_BYTES>>>(gxn, gxn, mask, x, gx);

    // 2) x1 = LN2(x'); x'' = x' + crossattn(x1, enc)
    ln_kernel<<<NROWS, 128>>>(gx, ln2g, ln2b, gxn);
    attn_kernel<<<attn_grid, 256, ATTN_SMEM_BYTES>>>(gxn, enc, nullptr, gx, gx);

    // 3) x1 = LN3(x''); out = x'' + relu(x1 W1 + b1) W2 + b2
    ln_kernel<<<NROWS, 128>>>(gx, ln3g, ln3b, gxn);
    gemm_kernel<true,  false><<<dim3(D_FF / 64,    NROWS / 64), 256>>>(
        gxn, W1, b1, nullptr, gh, NROWS, D_FF, D_MODEL);
    gemm_kernel<false, true ><<<dim3(D_MODEL / 64, NROWS / 64), 256>>>(
        gh, W2, b2, gx, out, NROWS, D_MODEL, D_FF);
}